// round 1
// baseline (speedup 1.0000x reference)
#include <cuda_runtime.h>

#define BB 4
#define CC 32
#define TT 1024
#define UU 32
#define HH 128

#define PTT 128     // prep t-tile
#define ITILE 8     // attention i-rows per block
#define JT 64       // v-phase j-tile staged in smem

// ---- scratch (device globals; no allocation allowed) ----
__device__ __align__(16) float g_q [BB*TT*UU];
__device__ __align__(16) float g_k [BB*TT*UU];   // k + bh folded in
__device__ __align__(16) float g_xT[BB*TT*CC];   // x transposed: [b][t][c]
__device__ __align__(16) float g_z [BB*TT*CC];   // x + v (pre-LN1), [b][t][c]

__device__ __forceinline__ float fast_tanh(float x){
    float y; asm("tanh.approx.f32 %0, %1;" : "=f"(y) : "f"(x)); return y;
}
__device__ __forceinline__ float wsum(float v){
    #pragma unroll
    for (int o = 16; o; o >>= 1) v += __shfl_xor_sync(0xffffffffu, v, o);
    return v;
}
__device__ __forceinline__ float wmax(float v){
    #pragma unroll
    for (int o = 16; o; o >>= 1) v = fmaxf(v, __shfl_xor_sync(0xffffffffu, v, o));
    return v;
}

// ============================================================
// Kernel 1: q = xt@Wt, k = xt@Wx + bh, xT = transpose(x)
// ============================================================
__global__ __launch_bounds__(256) void prep_kernel(
    const float* __restrict__ x, const float* __restrict__ Wt,
    const float* __restrict__ Wx, const float* __restrict__ bh)
{
    __shared__ float xs[CC][PTT+1];
    __shared__ float Wts[CC][UU];
    __shared__ float Wxs[CC][UU];
    int b = blockIdx.x, t0 = blockIdx.y * PTT, tid = threadIdx.x;

    for (int i = tid; i < CC*UU; i += 256){ Wts[i/UU][i%UU] = Wt[i]; Wxs[i/UU][i%UU] = Wx[i]; }
    for (int i = tid; i < CC*PTT; i += 256){
        int c = i / PTT, tl = i % PTT;
        xs[c][tl] = x[(b*CC + c)*TT + t0 + tl];
    }
    __syncthreads();

    int u = tid & 31, tw = tid >> 5;
    float bhv = bh[u];
    for (int tl = tw; tl < PTT; tl += 8){
        float q = 0.f, k = bhv;
        #pragma unroll
        for (int c = 0; c < CC; c++){
            float xv = xs[c][tl];
            q = fmaf(xv, Wts[c][u], q);
            k = fmaf(xv, Wxs[c][u], k);
        }
        int t = t0 + tl;
        g_q[(b*TT + t)*UU + u] = q;
        g_k[(b*TT + t)*UU + u] = k;
    }
    for (int i = tid; i < PTT*CC; i += 256){
        int tl = i / CC, c = i % CC;
        g_xT[(b*TT + t0 + tl)*CC + c] = xs[c][tl];
    }
}

// ============================================================
// Kernel 2: fused energy + softmax + a-write + v + residual
//   one block = 8 consecutive i-rows of one batch, 256 threads
// ============================================================
__global__ __launch_bounds__(256) void attn_kernel(
    const float* __restrict__ Wa, float* __restrict__ a_out)
{
    __shared__ __align__(16) float e_s[ITILE*TT];         // 32 KB (energies, then p)
    __shared__ __align__(16) union {
        struct { float q[ITILE*UU]; float wa[UU]; } pa;   // e-phase
        float xs[JT*CC];                                   // v-phase (8 KB)
    } un;

    int b   = blockIdx.x;
    int i0  = blockIdx.y * ITILE;
    int tid = threadIdx.x;
    int lane = tid & 31;
    int w    = tid >> 5;

    if (tid < ITILE*UU) un.pa.q[tid] = g_q[(b*TT + i0)*UU + tid];
    if (tid < UU)       un.pa.wa[tid] = Wa[tid];
    __syncthreads();

    // ---- e-phase: each thread owns 4 j's, k row in registers ----
    {
        const float4* q4  = (const float4*)un.pa.q;
        const float4* wa4 = (const float4*)un.pa.wa;
        for (int j = tid; j < TT; j += 256){
            const float4* kp = (const float4*)&g_k[(size_t)(b*TT + j)*UU];
            float4 kr[8];
            #pragma unroll
            for (int u = 0; u < 8; u++) kr[u] = kp[u];
            float e[ITILE];
            #pragma unroll
            for (int r = 0; r < ITILE; r++) e[r] = 0.f;
            #pragma unroll
            for (int u = 0; u < 8; u++){
                float4 wa = wa4[u];
                float4 kk = kr[u];
                #pragma unroll
                for (int r = 0; r < ITILE; r++){
                    float4 q = q4[r*8 + u];
                    e[r] = fmaf(wa.x, fast_tanh(q.x + kk.x), e[r]);
                    e[r] = fmaf(wa.y, fast_tanh(q.y + kk.y), e[r]);
                    e[r] = fmaf(wa.z, fast_tanh(q.z + kk.z), e[r]);
                    e[r] = fmaf(wa.w, fast_tanh(q.w + kk.w), e[r]);
                }
            }
            #pragma unroll
            for (int r = 0; r < ITILE; r++) e_s[r*TT + j] = e[r];
        }
    }
    __syncthreads();

    // ---- softmax per warp (warp w owns row i0+w) + write a ----
    float inv;
    {
        float4* er = (float4*)&e_s[w*TT];
        float m = -INFINITY;
        #pragma unroll
        for (int it = 0; it < 8; it++){
            float4 v = er[it*32 + lane];
            m = fmaxf(m, fmaxf(fmaxf(v.x, v.y), fmaxf(v.z, v.w)));
        }
        m = wmax(m);
        float s = 0.f;
        #pragma unroll
        for (int it = 0; it < 8; it++){
            float4 v = er[it*32 + lane];
            v.x = __expf(v.x - m); v.y = __expf(v.y - m);
            v.z = __expf(v.z - m); v.w = __expf(v.w - m);
            er[it*32 + lane] = v;
            s += (v.x + v.y) + (v.z + v.w);
        }
        s = wsum(s);
        inv = 1.f / (s + 1e-5f);   // reference: e / (sum + EPS_ATTN)
        float4* ar = (float4*)&a_out[(size_t)(b*TT + i0 + w)*TT];
        #pragma unroll
        for (int it = 0; it < 8; it++){
            float4 v = er[it*32 + lane];
            v.x *= inv; v.y *= inv; v.z *= inv; v.w *= inv;
            ar[it*32 + lane] = v;
        }
    }

    // ---- v-phase: v[i,c] = sum_j a_ij * xT[j,c], xT tiles staged in smem ----
    float4 vac = make_float4(0.f, 0.f, 0.f, 0.f);
    int c4 = lane & 7;   // float4 channel group
    int jr = lane >> 3;  // j subgroup 0..3
    const float4* xT4 = (const float4*)g_xT;
    for (int jt = 0; jt < TT; jt += JT){
        __syncthreads();   // previous tile fully consumed (and, first iter, p's visible)
        for (int i = tid; i < JT*8; i += 256)
            ((float4*)un.xs)[i] = xT4[(size_t)(b*TT + jt)*8 + i];
        __syncthreads();
        const float4* xs4 = (const float4*)un.xs;
        const float*  pe  = &e_s[w*TT + jt];
        #pragma unroll
        for (int jj = 0; jj < JT; jj += 4){
            int j = jj + jr;
            float a  = pe[j] * inv;
            float4 xv = xs4[j*8 + c4];
            vac.x = fmaf(a, xv.x, vac.x); vac.y = fmaf(a, xv.y, vac.y);
            vac.z = fmaf(a, xv.z, vac.z); vac.w = fmaf(a, xv.w, vac.w);
        }
    }
    // reduce the 4 j-subgroups
    #pragma unroll
    for (int o = 8; o <= 16; o <<= 1){
        vac.x += __shfl_xor_sync(0xffffffffu, vac.x, o);
        vac.y += __shfl_xor_sync(0xffffffffu, vac.y, o);
        vac.z += __shfl_xor_sync(0xffffffffu, vac.z, o);
        vac.w += __shfl_xor_sync(0xffffffffu, vac.w, o);
    }
    if (jr == 0){
        int t = i0 + w;
        float4 xv = xT4[(size_t)(b*TT + t)*8 + c4];
        float4 z;
        z.x = xv.x + vac.x; z.y = xv.y + vac.y;
        z.z = xv.z + vac.z; z.w = xv.w + vac.w;
        ((float4*)g_z)[(size_t)(b*TT + t)*8 + c4] = z;
    }
}

// ============================================================
// Kernel 3: LN1 -> FFN (relu) -> residual -> LN2 -> y2 (B,C,T)
//   warp per token t, lane = channel c
// ============================================================
__global__ __launch_bounds__(256) void ffn_kernel(
    const float* __restrict__ gamma1, const float* __restrict__ beta1,
    const float* __restrict__ W1, const float* __restrict__ b1,
    const float* __restrict__ W2, const float* __restrict__ b2,
    const float* __restrict__ gamma2, const float* __restrict__ beta2,
    float* __restrict__ y2_out)
{
    __shared__ float W1s[HH][CC+1];   // pad 33: conflict-free lane=h reads
    __shared__ float W2s[CC][HH+5];   // pad 133: conflict-free lane=c reads
    __shared__ float ys [8][CC];
    __shared__ float h1s[8][HH];
    __shared__ float y2s[CC][9];      // transpose staging, pad 9

    int b = blockIdx.x, t0 = blockIdx.y * 8, tid = threadIdx.x;
    int l = tid & 31, w = tid >> 5;

    for (int i = tid; i < HH*CC; i += 256) W1s[i/CC][i%CC] = W1[i];
    for (int i = tid; i < CC*HH; i += 256) W2s[i/HH][i%HH] = W2[i];
    __syncthreads();

    int t = t0 + w;
    float z = g_z[(b*TT + t)*CC + l];

    // LN1 over channels
    float mean = wsum(z) * (1.f/32.f);
    float d = z - mean;
    float var = wsum(d*d) * (1.f/32.f) + 1e-14f;
    float y = d * rsqrtf(var) * gamma1[l] + beta1[l];
    ys[w][l] = y;
    __syncwarp();

    // FF1: h1[h] = relu(sum_c y[c]*W1[h,c] + b1[h]); lane handles h = l+32k
    float a0 = b1[l], a1 = b1[l+32], a2 = b1[l+64], a3 = b1[l+96];
    #pragma unroll
    for (int c = 0; c < CC; c++){
        float yc = ys[w][c];
        a0 = fmaf(yc, W1s[l     ][c], a0);
        a1 = fmaf(yc, W1s[l + 32][c], a1);
        a2 = fmaf(yc, W1s[l + 64][c], a2);
        a3 = fmaf(yc, W1s[l + 96][c], a3);
    }
    h1s[w][l     ] = fmaxf(a0, 0.f);
    h1s[w][l + 32] = fmaxf(a1, 0.f);
    h1s[w][l + 64] = fmaxf(a2, 0.f);
    h1s[w][l + 96] = fmaxf(a3, 0.f);
    __syncwarp();

    // FF2: h2[c] = sum_h h1[h]*W2[c,h] + b2[c]
    float h2 = b2[l];
    #pragma unroll
    for (int h = 0; h < HH; h++) h2 = fmaf(h1s[w][h], W2s[l][h], h2);

    // residual + LN2
    float z2 = y + h2;
    float m2 = wsum(z2) * (1.f/32.f);
    float d2 = z2 - m2;
    float v2 = wsum(d2*d2) * (1.f/32.f) + 1e-14f;
    float y2 = d2 * rsqrtf(v2) * gamma2[l] + beta2[l];

    y2s[l][w] = y2;
    __syncthreads();
    {
        int c = tid >> 3, tl = tid & 7;
        y2_out[(b*CC + c)*TT + t0 + tl] = y2s[c][tl];
    }
}

// ============================================================
extern "C" void kernel_launch(void* const* d_in, const int* in_sizes, int n_in,
                              void* d_out, int out_size)
{
    const float* x      = (const float*)d_in[0];
    const float* Wt     = (const float*)d_in[1];
    const float* Wx     = (const float*)d_in[2];
    const float* bh     = (const float*)d_in[3];
    const float* Wa     = (const float*)d_in[4];
    // d_in[5] = ba: scalar added to every e, cancels exactly in softmax
    const float* gamma1 = (const float*)d_in[6];
    const float* beta1  = (const float*)d_in[7];
    const float* W1     = (const float*)d_in[8];
    const float* b1     = (const float*)d_in[9];
    const float* W2     = (const float*)d_in[10];
    const float* b2     = (const float*)d_in[11];
    const float* gamma2 = (const float*)d_in[12];
    const float* beta2  = (const float*)d_in[13];

    float* out    = (float*)d_out;
    float* y2_out = out;                  // (B,C,T) = 131072 floats
    float* a_out  = out + BB*CC*TT;       // (B,T,T) = 4194304 floats

    prep_kernel<<<dim3(BB, TT/PTT),   256>>>(x, Wt, Wx, bh);
    attn_kernel<<<dim3(BB, TT/ITILE), 256>>>(Wa, a_out);
    ffn_kernel <<<dim3(BB, TT/8),     256>>>(gamma1, beta1, W1, b1, W2, b2,
                                             gamma2, beta2, y2_out);
}